// round 4
// baseline (speedup 1.0000x reference)
#include <cuda_runtime.h>
#include <math.h>

#define BB 4
#define NN 8192
#define MM 8192
#define FEAT 64
#define KNN 16
#define K4 4
#define EPS 1e-5f
#define TILE 2048
#define QPB 16   // queries per mlp block

// ---------------- scratch (static device globals; no runtime alloc) ----------------
__device__ float g_w0f[FEAT * 3];
__device__ float g_b0f[FEAT];
__device__ float g_w1t[FEAT * FEAT];   // transposed + BN-folded: [cin][cout]
__device__ float g_b1f[FEAT];
__device__ int   g_knn[BB * NN * KNN];
__device__ float g_lft[BB * MM * FEAT]; // local_feat transposed to (B, M, FEAT)

// ---------------- kernel 0: fold BN into conv weights ----------------
__global__ void fold_kernel(const float* __restrict__ w0, const float* __restrict__ b0,
                            const float* __restrict__ g0, const float* __restrict__ be0,
                            const float* __restrict__ m0, const float* __restrict__ v0,
                            const float* __restrict__ w1, const float* __restrict__ b1,
                            const float* __restrict__ g1, const float* __restrict__ be1,
                            const float* __restrict__ m1, const float* __restrict__ v1) {
    int tid = threadIdx.x;
    if (tid < FEAT) {
        float inv0 = g0[tid] / sqrtf(v0[tid] + EPS);
        g_w0f[tid * 3 + 0] = w0[tid * 3 + 0] * inv0;
        g_w0f[tid * 3 + 1] = w0[tid * 3 + 1] * inv0;
        g_w0f[tid * 3 + 2] = w0[tid * 3 + 2] * inv0;
        g_b0f[tid] = (b0[tid] - m0[tid]) * inv0 + be0[tid];
        float inv1 = g1[tid] / sqrtf(v1[tid] + EPS);
        g_b1f[tid] = (b1[tid] - m1[tid]) * inv1 + be1[tid];
    }
    for (int i = tid; i < FEAT * FEAT; i += blockDim.x) {
        int cout = i / FEAT, cin = i % FEAT;
        float inv1 = g1[cout] / sqrtf(v1[cout] + EPS);
        g_w1t[cin * FEAT + cout] = w1[cout * FEAT + cin] * inv1;
    }
}

// ---------------- kernel 1: transpose local_feat (B,64,M) -> (B,M,64) ----------------
__global__ void __launch_bounds__(256) transpose_kernel(const float* __restrict__ lf) {
    __shared__ float tile[64][65];
    int b = blockIdx.y;
    int m0 = blockIdx.x * 64;
    int tid = threadIdx.x;
#pragma unroll
    for (int r = 0; r < 16; r++) {
        int c  = (tid >> 6) + (r << 2);
        int mm = tid & 63;
        tile[c][mm] = lf[((size_t)(b * FEAT + c)) * MM + m0 + mm];
    }
    __syncthreads();
#pragma unroll
    for (int r = 0; r < 16; r++) {
        int mm = (tid >> 6) + (r << 2);
        int c  = tid & 63;
        g_lft[((size_t)(b * MM + m0 + mm)) * FEAT + c] = tile[c][mm];
    }
}

// ---------------- kernel 2: fused KNN (top-16 by squared distance) ----------------
// Distance key replicates the reference fp32 arithmetic structure exactly:
//   q2 = (qx*qx + qy*qy) + qz*qz, o2 likewise
//   cross = fma(oz,qz, fma(oy,qy, ox*qx))
//   d2 = (q2 + o2) - (2*cross)
__device__ __forceinline__ float dist_key(float qx, float qy, float qz, float q2,
                                          const float4& o) {
    float cross = __fmaf_rn(o.z, qz, __fmaf_rn(o.y, qy, __fmul_rn(o.x, qx)));
    return __fsub_rn(__fadd_rn(q2, o.w), __fmul_rn(2.0f, cross));
}

__device__ __forceinline__ void topk_insert(float (&d)[KNN], int (&di)[KNN], float sv, int mv) {
    if (sv < d[KNN - 1]) {
#pragma unroll
        for (int jj = KNN - 1; jj > 0; --jj) {
            bool sh = sv < d[jj - 1];
            bool he = (sv < d[jj]) && !sh;
            float nd = sh ? d[jj - 1] : (he ? sv : d[jj]);
            int   ni = sh ? di[jj - 1] : (he ? mv : di[jj]);
            d[jj] = nd;
            di[jj] = ni;
        }
        if (sv < d[0]) { d[0] = sv; di[0] = mv; }
    }
}

__global__ void __launch_bounds__(128) knn_kernel(const float* __restrict__ orig,
                                                  const float* __restrict__ query) {
    __shared__ float4 tile[TILE];
    int b = blockIdx.y;
    int n = blockIdx.x * 128 + threadIdx.x;

    float qx = query[((size_t)(b * 3 + 0)) * NN + n];
    float qy = query[((size_t)(b * 3 + 1)) * NN + n];
    float qz = query[((size_t)(b * 3 + 2)) * NN + n];
    float q2 = __fadd_rn(__fadd_rn(__fmul_rn(qx, qx), __fmul_rn(qy, qy)), __fmul_rn(qz, qz));

    float d[KNN];
    int   di[KNN];
#pragma unroll
    for (int j = 0; j < KNN; j++) { d[j] = 3.0e38f; di[j] = 0; }

    const float* ox = orig + (size_t)(b * 3 + 0) * MM;
    const float* oy = ox + MM;
    const float* oz = oy + MM;

    for (int t0 = 0; t0 < MM; t0 += TILE) {
        __syncthreads();
        for (int i = threadIdx.x; i < TILE; i += 128) {
            float x = ox[t0 + i], y = oy[t0 + i], z = oz[t0 + i];
            float o2 = __fadd_rn(__fadd_rn(__fmul_rn(x, x), __fmul_rn(y, y)), __fmul_rn(z, z));
            tile[i] = make_float4(x, y, z, o2);
        }
        __syncthreads();
        for (int j = 0; j < TILE; j += 4) {
            float4 o0 = tile[j + 0];
            float4 o1 = tile[j + 1];
            float4 o2 = tile[j + 2];
            float4 o3 = tile[j + 3];
            float s0 = dist_key(qx, qy, qz, q2, o0);
            float s1 = dist_key(qx, qy, qz, q2, o1);
            float s2 = dist_key(qx, qy, qz, q2, o2);
            float s3 = dist_key(qx, qy, qz, q2, o3);
            float mn = fminf(fminf(s0, s1), fminf(s2, s3));
            // Group fast-path vote, then per-point votes so only points that
            // improve SOME lane's top-16 pay the 15-level insertion network.
            if (__any_sync(0xffffffffu, mn < d[KNN - 1])) {
                if (__any_sync(0xffffffffu, s0 < d[KNN - 1])) topk_insert(d, di, s0, t0 + j + 0);
                if (__any_sync(0xffffffffu, s1 < d[KNN - 1])) topk_insert(d, di, s1, t0 + j + 1);
                if (__any_sync(0xffffffffu, s2 < d[KNN - 1])) topk_insert(d, di, s2, t0 + j + 2);
                if (__any_sync(0xffffffffu, s3 < d[KNN - 1])) topk_insert(d, di, s3, t0 + j + 3);
            }
        }
    }
    int base = ((b * NN) + n) * KNN;
#pragma unroll
    for (int j = 0; j < KNN; j++) g_knn[base + j] = di[j];
}

// ---------------- kernel 3: fused MLP + gather + blend (QPB queries/block) ----------------
__global__ void __launch_bounds__(256) mlp_kernel(const float* __restrict__ orig,
                                                  const float* __restrict__ query,
                                                  const float* __restrict__ w2,
                                                  const float* __restrict__ b2,
                                                  float* __restrict__ out) {
    __shared__ float  w1s[FEAT * FEAT];
    __shared__ float  f0s[4][FEAT * K4];
    __shared__ float4 rel4[4][KNN];
    __shared__ int    idxs[4][KNN];
    __shared__ float  red[4][2][8];
    __shared__ float  outs[4][FEAT];

    int tid = threadIdx.x;
    int g = tid >> 6;
    int c = tid & 63;
    int b = blockIdx.y;

    for (int i = tid; i < FEAT * FEAT; i += 256) w1s[i] = g_w1t[i];

    // loop-invariant weights
    float w00 = g_w0f[c * 3 + 0], w01 = g_w0f[c * 3 + 1], w02 = g_w0f[c * 3 + 2];
    float bb0 = g_b0f[c];
    float bb1 = g_b1f[c];
    float w2a = w2[c], w2b = w2[FEAT + c];
    float b2v = b2[0];

    for (int it = 0; it < QPB / 4; ++it) {
        int n = blockIdx.x * QPB + it * 4 + g;

        if (c < KNN) idxs[g][c] = g_knn[(((size_t)b * NN) + n) * KNN + c];
        __syncthreads();  // S1: idxs visible (also covers w1s on it==0)

        // early patch-feat gather (hide LDG latency behind the MLP math)
        float p0 = g_lft[(((size_t)b * MM) + idxs[g][0]) * FEAT + c];
        float p1 = g_lft[(((size_t)b * MM) + idxs[g][1]) * FEAT + c];
        float p2 = g_lft[(((size_t)b * MM) + idxs[g][2]) * FEAT + c];
        float p3 = g_lft[(((size_t)b * MM) + idxs[g][3]) * FEAT + c];

        if (c < 48) {
            int j = c / 3;
            int a = c - j * 3;
            int m = idxs[g][j];
            float qa = query[((size_t)(b * 3 + a)) * NN + n];
            ((float*)&rel4[g][j])[a] = orig[((size_t)(b * 3 + a)) * MM + m] - qa;
        }
        __syncthreads();  // S2: rel4 visible

        // ---- layer 0 (3->64) + relu; feat_g max; keep k<4 for layer 1 ----
        float fg = 0.f;
        float f0k0 = 0.f, f0k1 = 0.f, f0k2 = 0.f, f0k3 = 0.f;
#pragma unroll
        for (int j = 0; j < KNN; j++) {
            float4 r = rel4[g][j];
            float f = fmaf(w00, r.x, fmaf(w01, r.y, fmaf(w02, r.z, bb0)));
            f = fmaxf(f, 0.f);
            fg = fmaxf(fg, f);
            if (j == 0) f0k0 = f;
            if (j == 1) f0k1 = f;
            if (j == 2) f0k2 = f;
            if (j == 3) f0k3 = f;
        }
        *(float4*)&f0s[g][c * 4] = make_float4(f0k0, f0k1, f0k2, f0k3);
        __syncthreads();  // S3: f0s visible

        // ---- layer 1 (64->64) for k<4 + relu ----
        float a0 = bb1, a1 = bb1, a2 = bb1, a3 = bb1;
#pragma unroll 8
        for (int cin = 0; cin < FEAT; ++cin) {
            float wv = w1s[cin * FEAT + c];
            float4 f = *(float4*)&f0s[g][cin * 4];
            a0 = fmaf(wv, f.x, a0);
            a1 = fmaf(wv, f.y, a1);
            a2 = fmaf(wv, f.z, a2);
            a3 = fmaf(wv, f.w, a3);
        }
        float r0 = fmaxf(a0, 0.f), r1 = fmaxf(a1, 0.f), r2 = fmaxf(a2, 0.f), r3 = fmaxf(a3, 0.f);

        // ---- sigmoid gate reduce over 64 channels ----
        float t0 = w2a * r0, t1 = w2a * r1, t2 = w2a * r2, t3 = w2a * r3;
        float u = w2b * fg;
#pragma unroll
        for (int off = 16; off; off >>= 1) {
            t0 += __shfl_down_sync(0xffffffffu, t0, off);
            t1 += __shfl_down_sync(0xffffffffu, t1, off);
            t2 += __shfl_down_sync(0xffffffffu, t2, off);
            t3 += __shfl_down_sync(0xffffffffu, t3, off);
            u  += __shfl_down_sync(0xffffffffu, u, off);
        }
        if ((c & 31) == 0) {
            float* rr = red[g][c >> 5];
            rr[0] = t0; rr[1] = t1; rr[2] = t2; rr[3] = t3; rr[4] = u;
        }
        __syncthreads();  // S4: red visible

        float base = red[g][0][4] + red[g][1][4] + b2v;
        float z0 = red[g][0][0] + red[g][1][0] + base;
        float z1 = red[g][0][1] + red[g][1][1] + base;
        float z2 = red[g][0][2] + red[g][1][2] + base;
        float z3 = red[g][0][3] + red[g][1][3] + base;
        float wg0 = 1.f / (1.f + expf(-z0));
        float wg1 = 1.f / (1.f + expf(-z1));
        float wg2 = 1.f / (1.f + expf(-z2));
        float wg3 = 1.f / (1.f + expf(-z3));

        float o = (1.f - wg0) * r0 + wg0 * p0;
        o      += (1.f - wg1) * r1 + wg1 * p1;
        o      += (1.f - wg2) * r2 + wg2 * p2;
        o      += (1.f - wg3) * r3 + wg3 * p3;

        outs[g][c] = o;
        __syncthreads();  // S5: outs visible (also separates next iter's idxs write)

        int c2 = tid >> 2, g2 = tid & 3;
        out[((size_t)(b * FEAT + c2)) * NN + blockIdx.x * QPB + it * 4 + g2] = outs[g2][c2];
        __syncthreads();  // S6: outs reads done before next iter overwrites shared state
    }
}

// ---------------- launch ----------------
extern "C" void kernel_launch(void* const* d_in, const int* in_sizes, int n_in,
                              void* d_out, int out_size) {
    const float* orig  = (const float*)d_in[0];
    const float* query = (const float*)d_in[1];
    const float* lf    = (const float*)d_in[2];
    const float* w0  = (const float*)d_in[3];
    const float* b0  = (const float*)d_in[4];
    const float* g0  = (const float*)d_in[5];
    const float* be0 = (const float*)d_in[6];
    const float* m0  = (const float*)d_in[7];
    const float* v0  = (const float*)d_in[8];
    const float* w1  = (const float*)d_in[9];
    const float* b1  = (const float*)d_in[10];
    const float* g1  = (const float*)d_in[11];
    const float* be1 = (const float*)d_in[12];
    const float* m1  = (const float*)d_in[13];
    const float* v1  = (const float*)d_in[14];
    const float* w2  = (const float*)d_in[15];
    const float* b2  = (const float*)d_in[16];
    float* out = (float*)d_out;

    fold_kernel<<<1, 256>>>(w0, b0, g0, be0, m0, v0, w1, b1, g1, be1, m1, v1);
    transpose_kernel<<<dim3(MM / 64, BB), 256>>>(lf);
    knn_kernel<<<dim3(NN / 128, BB), 128>>>(orig, query);
    mlp_kernel<<<dim3(NN / QPB, BB), 256>>>(orig, query, w2, b2, out);
}

// round 5
// speedup vs baseline: 1.4553x; 1.4553x over previous
#include <cuda_runtime.h>
#include <math.h>

#define BB 4
#define NN 8192
#define MM 8192
#define FEAT 64
#define KNN 16
#define K4 4
#define EPS 1e-5f
#define TILE 2048
#define QPB 16     // queries per mlp block
#define BINS 32768 // 15-bit morton (5 bits/dim)

// ---------------- scratch (static device globals; no runtime alloc) ----------------
__device__ float g_w0f[FEAT * 3];
__device__ float g_b0f[FEAT];
__device__ float g_w1t[FEAT * FEAT];
__device__ float g_b1f[FEAT];
__device__ int   g_knn[BB * NN * KNN];
__device__ float g_lft[BB * MM * FEAT];   // local_feat transposed to (B, M, FEAT)
__device__ int   g_hist[BB][BINS];
__device__ int   g_base[BB][BINS];
__device__ unsigned short g_key[BB][NN];
__device__ int   g_perm[BB][NN];          // sorted pos -> original n
__device__ float g_qs[BB][3][NN];         // morton-reordered query coords (SoA)

// ---------------- kernel 0: fold BN into conv weights + zero histogram ----------------
__global__ void fold_kernel(const float* __restrict__ w0, const float* __restrict__ b0,
                            const float* __restrict__ g0, const float* __restrict__ be0,
                            const float* __restrict__ m0, const float* __restrict__ v0,
                            const float* __restrict__ w1, const float* __restrict__ b1,
                            const float* __restrict__ g1, const float* __restrict__ be1,
                            const float* __restrict__ m1, const float* __restrict__ v1) {
    int tid = threadIdx.x;
    if (tid < FEAT) {
        float inv0 = g0[tid] / sqrtf(v0[tid] + EPS);
        g_w0f[tid * 3 + 0] = w0[tid * 3 + 0] * inv0;
        g_w0f[tid * 3 + 1] = w0[tid * 3 + 1] * inv0;
        g_w0f[tid * 3 + 2] = w0[tid * 3 + 2] * inv0;
        g_b0f[tid] = (b0[tid] - m0[tid]) * inv0 + be0[tid];
        float inv1 = g1[tid] / sqrtf(v1[tid] + EPS);
        g_b1f[tid] = (b1[tid] - m1[tid]) * inv1 + be1[tid];
    }
    for (int i = tid; i < FEAT * FEAT; i += blockDim.x) {
        int cout = i / FEAT, cin = i % FEAT;
        float inv1 = g1[cout] / sqrtf(v1[cout] + EPS);
        g_w1t[cin * FEAT + cout] = w1[cout * FEAT + cin] * inv1;
    }
    int* h = &g_hist[0][0];
    for (int i = tid; i < BB * BINS; i += blockDim.x) h[i] = 0;
}

// ---------------- morton sort: key+hist, scan, scatter ----------------
__device__ __forceinline__ int spread5(int v) {
    return (v & 1) | ((v & 2) << 2) | ((v & 4) << 4) | ((v & 8) << 6) | ((v & 16) << 8);
}

__global__ void __launch_bounds__(256) key_kernel(const float* __restrict__ q) {
    int b = blockIdx.y;
    int n = blockIdx.x * 256 + threadIdx.x;
    float x = q[((size_t)(b * 3 + 0)) * NN + n];
    float y = q[((size_t)(b * 3 + 1)) * NN + n];
    float z = q[((size_t)(b * 3 + 2)) * NN + n];
    int ux = min(31, max(0, (int)((x + 4.0f) * 4.0f)));
    int uy = min(31, max(0, (int)((y + 4.0f) * 4.0f)));
    int uz = min(31, max(0, (int)((z + 4.0f) * 4.0f)));
    int key = spread5(ux) | (spread5(uy) << 1) | (spread5(uz) << 2);
    g_key[b][n] = (unsigned short)key;
    atomicAdd(&g_hist[b][key], 1);
}

__global__ void __launch_bounds__(1024) scan_kernel() {
    __shared__ int ps[1024];
    int b = blockIdx.x;
    int t = threadIdx.x;
    int s = 0;
#pragma unroll
    for (int i = 0; i < BINS / 1024; i++) s += g_hist[b][t * (BINS / 1024) + i];
    ps[t] = s;
    __syncthreads();
    for (int off = 1; off < 1024; off <<= 1) {
        int v = (t >= off) ? ps[t - off] : 0;
        __syncthreads();
        ps[t] += v;
        __syncthreads();
    }
    int run = ps[t] - s;  // exclusive base for this thread's bin range
#pragma unroll
    for (int i = 0; i < BINS / 1024; i++) {
        int bin = t * (BINS / 1024) + i;
        g_base[b][bin] = run;
        run += g_hist[b][bin];
    }
}

__global__ void __launch_bounds__(256) scatter_kernel(const float* __restrict__ q) {
    int b = blockIdx.y;
    int n = blockIdx.x * 256 + threadIdx.x;
    int key = g_key[b][n];
    int pos = atomicAdd(&g_base[b][key], 1);
    g_perm[b][pos] = n;
    g_qs[b][0][pos] = q[((size_t)(b * 3 + 0)) * NN + n];
    g_qs[b][1][pos] = q[((size_t)(b * 3 + 1)) * NN + n];
    g_qs[b][2][pos] = q[((size_t)(b * 3 + 2)) * NN + n];
}

// ---------------- kernel 1: transpose local_feat (B,64,M) -> (B,M,64) ----------------
__global__ void __launch_bounds__(256) transpose_kernel(const float* __restrict__ lf) {
    __shared__ float tile[64][65];
    int b = blockIdx.y;
    int m0 = blockIdx.x * 64;
    int tid = threadIdx.x;
#pragma unroll
    for (int r = 0; r < 16; r++) {
        int c  = (tid >> 6) + (r << 2);
        int mm = tid & 63;
        tile[c][mm] = lf[((size_t)(b * FEAT + c)) * MM + m0 + mm];
    }
    __syncthreads();
#pragma unroll
    for (int r = 0; r < 16; r++) {
        int mm = (tid >> 6) + (r << 2);
        int c  = tid & 63;
        g_lft[((size_t)(b * MM + m0 + mm)) * FEAT + c] = tile[c][mm];
    }
}

// ---------------- kernel 2: fused KNN (top-16, queries in morton order) ----------------
__device__ __forceinline__ float dist_key(float qx, float qy, float qz, float q2,
                                          const float4& o) {
    float cross = __fmaf_rn(o.z, qz, __fmaf_rn(o.y, qy, __fmul_rn(o.x, qx)));
    return __fsub_rn(__fadd_rn(q2, o.w), __fmul_rn(2.0f, cross));
}

__device__ __forceinline__ void topk_insert(float (&d)[KNN], int (&di)[KNN], float sv, int mv) {
    if (sv < d[KNN - 1]) {
#pragma unroll
        for (int jj = KNN - 1; jj > 0; --jj) {
            bool sh = sv < d[jj - 1];
            bool he = (sv < d[jj]) && !sh;
            float nd = sh ? d[jj - 1] : (he ? sv : d[jj]);
            int   ni = sh ? di[jj - 1] : (he ? mv : di[jj]);
            d[jj] = nd;
            di[jj] = ni;
        }
        if (sv < d[0]) { d[0] = sv; di[0] = mv; }
    }
}

__global__ void __launch_bounds__(128) knn_kernel(const float* __restrict__ orig) {
    __shared__ float4 tile[TILE];
    int b = blockIdx.y;
    int n = blockIdx.x * 128 + threadIdx.x;   // sorted position

    float qx = g_qs[b][0][n];
    float qy = g_qs[b][1][n];
    float qz = g_qs[b][2][n];
    float q2 = __fadd_rn(__fadd_rn(__fmul_rn(qx, qx), __fmul_rn(qy, qy)), __fmul_rn(qz, qz));

    float d[KNN];
    int   di[KNN];
#pragma unroll
    for (int j = 0; j < KNN; j++) { d[j] = 3.0e38f; di[j] = 0; }

    const float* ox = orig + (size_t)(b * 3 + 0) * MM;
    const float* oy = ox + MM;
    const float* oz = oy + MM;

    for (int t0 = 0; t0 < MM; t0 += TILE) {
        __syncthreads();
        for (int i = threadIdx.x; i < TILE; i += 128) {
            float x = ox[t0 + i], y = oy[t0 + i], z = oz[t0 + i];
            float o2 = __fadd_rn(__fadd_rn(__fmul_rn(x, x), __fmul_rn(y, y)), __fmul_rn(z, z));
            tile[i] = make_float4(x, y, z, o2);
        }
        __syncthreads();
        for (int j = 0; j < TILE; j += 4) {
            float4 o0 = tile[j + 0];
            float4 o1 = tile[j + 1];
            float4 o2 = tile[j + 2];
            float4 o3 = tile[j + 3];
            float s0 = dist_key(qx, qy, qz, q2, o0);
            float s1 = dist_key(qx, qy, qz, q2, o1);
            float s2 = dist_key(qx, qy, qz, q2, o2);
            float s3 = dist_key(qx, qy, qz, q2, o3);
            float mn = fminf(fminf(s0, s1), fminf(s2, s3));
            if (__any_sync(0xffffffffu, mn < d[KNN - 1])) {
                if (__any_sync(0xffffffffu, s0 < d[KNN - 1])) topk_insert(d, di, s0, t0 + j + 0);
                if (__any_sync(0xffffffffu, s1 < d[KNN - 1])) topk_insert(d, di, s1, t0 + j + 1);
                if (__any_sync(0xffffffffu, s2 < d[KNN - 1])) topk_insert(d, di, s2, t0 + j + 2);
                if (__any_sync(0xffffffffu, s3 < d[KNN - 1])) topk_insert(d, di, s3, t0 + j + 3);
            }
        }
    }
    int orign = g_perm[b][n];
    int base = ((b * NN) + orign) * KNN;
#pragma unroll
    for (int j = 0; j < KNN; j++) g_knn[base + j] = di[j];
}

// ---------------- kernel 3: fused MLP + gather + blend (QPB queries/block) ----------------
__global__ void __launch_bounds__(256) mlp_kernel(const float* __restrict__ orig,
                                                  const float* __restrict__ query,
                                                  const float* __restrict__ w2,
                                                  const float* __restrict__ b2,
                                                  float* __restrict__ out) {
    __shared__ float  w1s[FEAT * FEAT];
    __shared__ float  f0s[4][FEAT * K4];
    __shared__ float4 rel4[4][KNN];
    __shared__ int    idxs[4][KNN];
    __shared__ float  red[4][2][8];
    __shared__ float  outs[4][FEAT];

    int tid = threadIdx.x;
    int g = tid >> 6;
    int c = tid & 63;
    int b = blockIdx.y;

    for (int i = tid; i < FEAT * FEAT; i += 256) w1s[i] = g_w1t[i];

    float w00 = g_w0f[c * 3 + 0], w01 = g_w0f[c * 3 + 1], w02 = g_w0f[c * 3 + 2];
    float bb0 = g_b0f[c];
    float bb1 = g_b1f[c];
    float w2a = w2[c], w2b = w2[FEAT + c];
    float b2v = b2[0];

    for (int it = 0; it < QPB / 4; ++it) {
        int n = blockIdx.x * QPB + it * 4 + g;

        if (c < KNN) idxs[g][c] = g_knn[(((size_t)b * NN) + n) * KNN + c];
        __syncthreads();

        float p0 = g_lft[(((size_t)b * MM) + idxs[g][0]) * FEAT + c];
        float p1 = g_lft[(((size_t)b * MM) + idxs[g][1]) * FEAT + c];
        float p2 = g_lft[(((size_t)b * MM) + idxs[g][2]) * FEAT + c];
        float p3 = g_lft[(((size_t)b * MM) + idxs[g][3]) * FEAT + c];

        if (c < 48) {
            int j = c / 3;
            int a = c - j * 3;
            int m = idxs[g][j];
            float qa = query[((size_t)(b * 3 + a)) * NN + n];
            ((float*)&rel4[g][j])[a] = orig[((size_t)(b * 3 + a)) * MM + m] - qa;
        }
        __syncthreads();

        float fg = 0.f;
        float f0k0 = 0.f, f0k1 = 0.f, f0k2 = 0.f, f0k3 = 0.f;
#pragma unroll
        for (int j = 0; j < KNN; j++) {
            float4 r = rel4[g][j];
            float f = fmaf(w00, r.x, fmaf(w01, r.y, fmaf(w02, r.z, bb0)));
            f = fmaxf(f, 0.f);
            fg = fmaxf(fg, f);
            if (j == 0) f0k0 = f;
            if (j == 1) f0k1 = f;
            if (j == 2) f0k2 = f;
            if (j == 3) f0k3 = f;
        }
        *(float4*)&f0s[g][c * 4] = make_float4(f0k0, f0k1, f0k2, f0k3);
        __syncthreads();

        float a0 = bb1, a1 = bb1, a2 = bb1, a3 = bb1;
#pragma unroll 8
        for (int cin = 0; cin < FEAT; ++cin) {
            float wv = w1s[cin * FEAT + c];
            float4 f = *(float4*)&f0s[g][cin * 4];
            a0 = fmaf(wv, f.x, a0);
            a1 = fmaf(wv, f.y, a1);
            a2 = fmaf(wv, f.z, a2);
            a3 = fmaf(wv, f.w, a3);
        }
        float r0 = fmaxf(a0, 0.f), r1 = fmaxf(a1, 0.f), r2 = fmaxf(a2, 0.f), r3 = fmaxf(a3, 0.f);

        float t0 = w2a * r0, t1 = w2a * r1, t2 = w2a * r2, t3 = w2a * r3;
        float u = w2b * fg;
#pragma unroll
        for (int off = 16; off; off >>= 1) {
            t0 += __shfl_down_sync(0xffffffffu, t0, off);
            t1 += __shfl_down_sync(0xffffffffu, t1, off);
            t2 += __shfl_down_sync(0xffffffffu, t2, off);
            t3 += __shfl_down_sync(0xffffffffu, t3, off);
            u  += __shfl_down_sync(0xffffffffu, u, off);
        }
        if ((c & 31) == 0) {
            float* rr = red[g][c >> 5];
            rr[0] = t0; rr[1] = t1; rr[2] = t2; rr[3] = t3; rr[4] = u;
        }
        __syncthreads();

        float base = red[g][0][4] + red[g][1][4] + b2v;
        float z0 = red[g][0][0] + red[g][1][0] + base;
        float z1 = red[g][0][1] + red[g][1][1] + base;
        float z2 = red[g][0][2] + red[g][1][2] + base;
        float z3 = red[g][0][3] + red[g][1][3] + base;
        float wg0 = 1.f / (1.f + expf(-z0));
        float wg1 = 1.f / (1.f + expf(-z1));
        float wg2 = 1.f / (1.f + expf(-z2));
        float wg3 = 1.f / (1.f + expf(-z3));

        float o = (1.f - wg0) * r0 + wg0 * p0;
        o      += (1.f - wg1) * r1 + wg1 * p1;
        o      += (1.f - wg2) * r2 + wg2 * p2;
        o      += (1.f - wg3) * r3 + wg3 * p3;

        outs[g][c] = o;
        __syncthreads();

        int c2 = tid >> 2, g2 = tid & 3;
        out[((size_t)(b * FEAT + c2)) * NN + blockIdx.x * QPB + it * 4 + g2] = outs[g2][c2];
        __syncthreads();
    }
}

// ---------------- launch ----------------
extern "C" void kernel_launch(void* const* d_in, const int* in_sizes, int n_in,
                              void* d_out, int out_size) {
    const float* orig  = (const float*)d_in[0];
    const float* query = (const float*)d_in[1];
    const float* lf    = (const float*)d_in[2];
    const float* w0  = (const float*)d_in[3];
    const float* b0  = (const float*)d_in[4];
    const float* g0  = (const float*)d_in[5];
    const float* be0 = (const float*)d_in[6];
    const float* m0  = (const float*)d_in[7];
    const float* v0  = (const float*)d_in[8];
    const float* w1  = (const float*)d_in[9];
    const float* b1  = (const float*)d_in[10];
    const float* g1  = (const float*)d_in[11];
    const float* be1 = (const float*)d_in[12];
    const float* m1  = (const float*)d_in[13];
    const float* v1  = (const float*)d_in[14];
    const float* w2  = (const float*)d_in[15];
    const float* b2  = (const float*)d_in[16];
    float* out = (float*)d_out;

    fold_kernel<<<1, 256>>>(w0, b0, g0, be0, m0, v0, w1, b1, g1, be1, m1, v1);
    key_kernel<<<dim3(NN / 256, BB), 256>>>(query);
    scan_kernel<<<BB, 1024>>>();
    scatter_kernel<<<dim3(NN / 256, BB), 256>>>(query);
    transpose_kernel<<<dim3(MM / 64, BB), 256>>>(lf);
    knn_kernel<<<dim3(NN / 128, BB), 128>>>(orig);
    mlp_kernel<<<dim3(NN / QPB, BB), 256>>>(orig, query, w2, b2, out);
}